// round 1
// baseline (speedup 1.0000x reference)
#include <cuda_runtime.h>
#include <math.h>

#define C_DIM   512
#define CH_DIM  128
#define HW_DIM  9216           // 96*96
#define B_DIM   16
#define TILE_PIX 128
#define KC       8             // channels per SMEM chunk

// transposed w1 scratch: wT[c][o]  (256 KB, __device__ global — no allocs)
__device__ float g_wT[C_DIM * CH_DIM];

__global__ void lcs_transpose_w1(const float* __restrict__ w1) {
    int idx = blockIdx.x * blockDim.x + threadIdx.x;   // 0 .. 65535
    int c = idx >> 7;
    int o = idx & 127;
    g_wT[c * CH_DIM + o] = w1[o * C_DIM + c];
}

__device__ __forceinline__ void ffma2(unsigned long long& d,
                                      unsigned long long a,
                                      unsigned long long b) {
    asm("fma.rn.f32x2 %0, %1, %2, %0;" : "+l"(d) : "l"(a), "l"(b));
}

__global__ __launch_bounds__(256, 2)
void lcs_fused(const float* __restrict__ x,
               const float* __restrict__ b1,
               const float* __restrict__ w2,
               const float* __restrict__ b2,
               float* __restrict__ out) {
    __shared__ __align__(16) float  x_s[KC][TILE_PIX];        // 4 KB
    __shared__ __align__(16) float2 w_s[KC][CH_DIM];          // 8 KB (duplicated pairs)
    __shared__ float logit_d[TILE_PIX];
    __shared__ __align__(16) float m0_s[TILE_PIX];
    __shared__ __align__(16) float m1_s[TILE_PIX];

    const int tid  = threadIdx.x;
    const int blk  = blockIdx.x;                    // 0 .. B*72-1
    const int b    = blk / (HW_DIM / TILE_PIX);
    const int tile = blk % (HW_DIM / TILE_PIX);
    const int pix0 = tile * TILE_PIX;

    const float* xb = x + (size_t)b * C_DIM * HW_DIM + pix0;

    const int io = tid >> 4;        // 0..15 -> out group
    const int ip = tid & 15;        // 0..15 -> pixel group
    const int o0 = io * 8;
    const int p0 = ip * 8;

    // 8 outs x 4 pixel-pairs packed f32x2 accumulators
    unsigned long long acc[8][4];
#pragma unroll
    for (int i = 0; i < 8; i++)
#pragma unroll
        for (int j = 0; j < 4; j++) acc[i][j] = 0ULL;

    const int lrow = tid >> 5;   // 0..7  : channel row within chunk
    const int lc4  = tid & 31;   // 0..31 : float4 column

    for (int c0 = 0; c0 < C_DIM; c0 += KC) {
        __syncthreads();
        // stage x chunk: 8 rows x 128 pixels (one float4 per thread, coalesced)
        float4 xv = *(const float4*)(xb + (size_t)(c0 + lrow) * HW_DIM + lc4 * 4);
        *(float4*)&x_s[lrow][lc4 * 4] = xv;
        // stage w chunk duplicated into f32x2 pairs
        float4 wv = *(const float4*)(g_wT + (c0 + lrow) * CH_DIM + lc4 * 4);
        w_s[lrow][lc4 * 4 + 0] = make_float2(wv.x, wv.x);
        w_s[lrow][lc4 * 4 + 1] = make_float2(wv.y, wv.y);
        w_s[lrow][lc4 * 4 + 2] = make_float2(wv.z, wv.z);
        w_s[lrow][lc4 * 4 + 3] = make_float2(wv.w, wv.w);
        __syncthreads();

#pragma unroll
        for (int ci = 0; ci < KC; ci++) {
            unsigned long long wp[8];
            const ulonglong2* wr = (const ulonglong2*)&w_s[ci][o0];
#pragma unroll
            for (int q = 0; q < 4; q++) {
                ulonglong2 t = wr[q];
                wp[2 * q]     = t.x;
                wp[2 * q + 1] = t.y;
            }
            unsigned long long xp[4];
            const ulonglong2* xr = (const ulonglong2*)&x_s[ci][p0];
#pragma unroll
            for (int q = 0; q < 2; q++) {
                ulonglong2 t = xr[q];
                xp[2 * q]     = t.x;
                xp[2 * q + 1] = t.y;
            }
#pragma unroll
            for (int i = 0; i < 8; i++)
#pragma unroll
                for (int j = 0; j < 4; j++)
                    ffma2(acc[i][j], wp[i], xp[j]);
        }
    }

    // ---- epilogue: logits, softmax ----
    if (tid < TILE_PIX) logit_d[tid] = 0.0f;

    float b1v[8], wdv[8];
#pragma unroll
    for (int i = 0; i < 8; i++) {
        b1v[i] = b1[o0 + i];
        wdv[i] = w2[o0 + i] - w2[CH_DIM + o0 + i];   // w2[0][o] - w2[1][o]
    }
    __syncthreads();

#pragma unroll
    for (int jp = 0; jp < 4; jp++) {
        float part_lo = 0.0f, part_hi = 0.0f;
#pragma unroll
        for (int i = 0; i < 8; i++) {
            float2 av = *reinterpret_cast<float2*>(&acc[i][jp]);
            part_lo += wdv[i] * fmaxf(av.x + b1v[i], 0.0f);
            part_hi += wdv[i] * fmaxf(av.y + b1v[i], 0.0f);
        }
        atomicAdd(&logit_d[p0 + 2 * jp],     part_lo);
        atomicAdd(&logit_d[p0 + 2 * jp + 1], part_hi);
    }
    __syncthreads();

    const size_t OFFX = (size_t)B_DIM * C_DIM * HW_DIM;     // x1 region offset
    if (tid < TILE_PIX) {
        float d  = logit_d[tid] + (b2[0] - b2[1]);          // l0 - l1
        float m0 = 1.0f / (1.0f + expf(-d));                // softmax over 2
        float m1 = 1.0f - m0;
        m0_s[tid] = m0;
        m1_s[tid] = m1;
        // m region: base 2*OFFX, layout (B, 2, H, W)
        float* mout = out + 2 * OFFX + (size_t)b * 2 * HW_DIM + pix0 + tid;
        mout[0]      = m0;
        mout[HW_DIM] = m1;
    }
    __syncthreads();

    // ---- multiply sweep: x0 = x*m0, x1 = x*m1 (x tile re-read, L2-resident) ----
    float* out0 = out + (size_t)b * C_DIM * HW_DIM + pix0;
    float* out1 = out0 + OFFX;
    const float4* m0v4 = (const float4*)m0_s;
    const float4* m1v4 = (const float4*)m1_s;

    for (int it = tid; it < C_DIM * (TILE_PIX / 4); it += 256) {
        int c    = it >> 5;
        int col4 = it & 31;
        size_t off = (size_t)c * HW_DIM + col4 * 4;
        float4 xv  = *(const float4*)(xb + off);
        float4 m0v = m0v4[col4];
        float4 m1v = m1v4[col4];
        float4 r0 = make_float4(xv.x * m0v.x, xv.y * m0v.y, xv.z * m0v.z, xv.w * m0v.w);
        float4 r1 = make_float4(xv.x * m1v.x, xv.y * m1v.y, xv.z * m1v.z, xv.w * m1v.w);
        *(float4*)(out0 + off) = r0;
        *(float4*)(out1 + off) = r1;
    }
}

extern "C" void kernel_launch(void* const* d_in, const int* in_sizes, int n_in,
                              void* d_out, int out_size) {
    const float* x  = (const float*)d_in[0];
    const float* w1 = (const float*)d_in[1];
    const float* b1 = (const float*)d_in[2];
    const float* w2 = (const float*)d_in[3];
    const float* b2 = (const float*)d_in[4];
    float* out = (float*)d_out;

    lcs_transpose_w1<<<(C_DIM * CH_DIM) / 256, 256>>>(w1);

    int nblocks = B_DIM * (HW_DIM / TILE_PIX);   // 16 * 72 = 1152
    lcs_fused<<<nblocks, 256>>>(x, b1, w2, b2, out);
}

// round 2
// speedup vs baseline: 1.0066x; 1.0066x over previous
#include <cuda_runtime.h>
#include <math.h>

#define C_DIM   512
#define CH_DIM  128
#define HW_DIM  9216           // 96*96
#define B_DIM   16
#define TILE_PIX 128
#define KC       8             // channels per SMEM chunk

// transposed w1 scratch: wT[c][o]  (256 KB, __device__ global — no allocs)
__device__ float g_wT[C_DIM * CH_DIM];

__global__ void lcs_transpose_w1(const float* __restrict__ w1) {
    int idx = blockIdx.x * blockDim.x + threadIdx.x;   // 0 .. 65535
    int c = idx >> 7;
    int o = idx & 127;
    g_wT[c * CH_DIM + o] = w1[o * C_DIM + c];
}

__device__ __forceinline__ void ffma2(unsigned long long& d,
                                      unsigned long long a,
                                      unsigned long long b) {
    asm("fma.rn.f32x2 %0, %1, %2, %0;" : "+l"(d) : "l"(a), "l"(b));
}

__global__ __launch_bounds__(256, 2)
void lcs_fused(const float* __restrict__ x,
               const float* __restrict__ b1,
               const float* __restrict__ w2,
               const float* __restrict__ b2,
               float* __restrict__ out) {
    __shared__ __align__(16) float  x_s[KC][TILE_PIX];        // 4 KB
    __shared__ __align__(16) float2 w_s[KC][CH_DIM];          // 8 KB (duplicated pairs)
    __shared__ float logit_d[TILE_PIX];
    __shared__ __align__(16) float m0_s[TILE_PIX];
    __shared__ __align__(16) float m1_s[TILE_PIX];

    const int tid  = threadIdx.x;
    const int blk  = blockIdx.x;                    // 0 .. B*72-1
    const int b    = blk / (HW_DIM / TILE_PIX);
    const int tile = blk % (HW_DIM / TILE_PIX);
    const int pix0 = tile * TILE_PIX;

    const float* xb = x + (size_t)b * C_DIM * HW_DIM + pix0;

    const int io = tid >> 4;        // 0..15 -> out group
    const int ip = tid & 15;        // 0..15 -> pixel group
    const int o0 = io * 8;
    const int p0 = ip * 8;

    // 8 outs x 4 pixel-pairs packed f32x2 accumulators
    unsigned long long acc[8][4];
#pragma unroll
    for (int i = 0; i < 8; i++)
#pragma unroll
        for (int j = 0; j < 4; j++) acc[i][j] = 0ULL;

    const int lrow = tid >> 5;   // 0..7  : channel row within chunk
    const int lc4  = tid & 31;   // 0..31 : float4 column

    for (int c0 = 0; c0 < C_DIM; c0 += KC) {
        __syncthreads();
        // stage x chunk: 8 rows x 128 pixels (one float4 per thread, coalesced)
        float4 xv = *(const float4*)(xb + (size_t)(c0 + lrow) * HW_DIM + lc4 * 4);
        *(float4*)&x_s[lrow][lc4 * 4] = xv;
        // stage w chunk duplicated into f32x2 pairs
        float4 wv = *(const float4*)(g_wT + (c0 + lrow) * CH_DIM + lc4 * 4);
        w_s[lrow][lc4 * 4 + 0] = make_float2(wv.x, wv.x);
        w_s[lrow][lc4 * 4 + 1] = make_float2(wv.y, wv.y);
        w_s[lrow][lc4 * 4 + 2] = make_float2(wv.z, wv.z);
        w_s[lrow][lc4 * 4 + 3] = make_float2(wv.w, wv.w);
        __syncthreads();

#pragma unroll
        for (int ci = 0; ci < KC; ci++) {
            unsigned long long wp[8];
            const ulonglong2* wr = (const ulonglong2*)&w_s[ci][o0];
#pragma unroll
            for (int q = 0; q < 4; q++) {
                ulonglong2 t = wr[q];
                wp[2 * q]     = t.x;
                wp[2 * q + 1] = t.y;
            }
            unsigned long long xp[4];
            const ulonglong2* xr = (const ulonglong2*)&x_s[ci][p0];
#pragma unroll
            for (int q = 0; q < 2; q++) {
                ulonglong2 t = xr[q];
                xp[2 * q]     = t.x;
                xp[2 * q + 1] = t.y;
            }
#pragma unroll
            for (int i = 0; i < 8; i++)
#pragma unroll
                for (int j = 0; j < 4; j++)
                    ffma2(acc[i][j], wp[i], xp[j]);
        }
    }

    // ---- epilogue: logits, softmax ----
    if (tid < TILE_PIX) logit_d[tid] = 0.0f;

    float b1v[8], wdv[8];
#pragma unroll
    for (int i = 0; i < 8; i++) {
        b1v[i] = b1[o0 + i];
        wdv[i] = w2[o0 + i] - w2[CH_DIM + o0 + i];   // w2[0][o] - w2[1][o]
    }
    __syncthreads();

#pragma unroll
    for (int jp = 0; jp < 4; jp++) {
        float part_lo = 0.0f, part_hi = 0.0f;
#pragma unroll
        for (int i = 0; i < 8; i++) {
            float2 av = *reinterpret_cast<float2*>(&acc[i][jp]);
            part_lo += wdv[i] * fmaxf(av.x + b1v[i], 0.0f);
            part_hi += wdv[i] * fmaxf(av.y + b1v[i], 0.0f);
        }
        atomicAdd(&logit_d[p0 + 2 * jp],     part_lo);
        atomicAdd(&logit_d[p0 + 2 * jp + 1], part_hi);
    }
    __syncthreads();

    const size_t OFFX = (size_t)B_DIM * C_DIM * HW_DIM;     // x1 region offset
    if (tid < TILE_PIX) {
        float d  = logit_d[tid] + (b2[0] - b2[1]);          // l0 - l1
        float m0 = 1.0f / (1.0f + expf(-d));                // softmax over 2
        float m1 = 1.0f - m0;
        m0_s[tid] = m0;
        m1_s[tid] = m1;
        // m region: base 2*OFFX, layout (B, 2, H, W)
        float* mout = out + 2 * OFFX + (size_t)b * 2 * HW_DIM + pix0 + tid;
        mout[0]      = m0;
        mout[HW_DIM] = m1;
    }
    __syncthreads();

    // ---- multiply sweep: x0 = x*m0, x1 = x*m1 (x tile re-read, L2-resident) ----
    float* out0 = out + (size_t)b * C_DIM * HW_DIM + pix0;
    float* out1 = out0 + OFFX;
    const float4* m0v4 = (const float4*)m0_s;
    const float4* m1v4 = (const float4*)m1_s;

    for (int it = tid; it < C_DIM * (TILE_PIX / 4); it += 256) {
        int c    = it >> 5;
        int col4 = it & 31;
        size_t off = (size_t)c * HW_DIM + col4 * 4;
        float4 xv  = *(const float4*)(xb + off);
        float4 m0v = m0v4[col4];
        float4 m1v = m1v4[col4];
        float4 r0 = make_float4(xv.x * m0v.x, xv.y * m0v.y, xv.z * m0v.z, xv.w * m0v.w);
        float4 r1 = make_float4(xv.x * m1v.x, xv.y * m1v.y, xv.z * m1v.z, xv.w * m1v.w);
        *(float4*)(out0 + off) = r0;
        *(float4*)(out1 + off) = r1;
    }
}

extern "C" void kernel_launch(void* const* d_in, const int* in_sizes, int n_in,
                              void* d_out, int out_size) {
    const float* x  = (const float*)d_in[0];
    const float* w1 = (const float*)d_in[1];
    const float* b1 = (const float*)d_in[2];
    const float* w2 = (const float*)d_in[3];
    const float* b2 = (const float*)d_in[4];
    float* out = (float*)d_out;

    lcs_transpose_w1<<<(C_DIM * CH_DIM) / 256, 256>>>(w1);

    int nblocks = B_DIM * (HW_DIM / TILE_PIX);   // 16 * 72 = 1152
    lcs_fused<<<nblocks, 256>>>(x, b1, w2, b2, out);
}

// round 7
// speedup vs baseline: 2.2784x; 2.2634x over previous
#include <cuda_runtime.h>
#include <cuda_bf16.h>
#include <cstdint>
#include <math.h>

#define C_DIM   512
#define CH_DIM  128
#define HW_DIM  9216
#define B_DIM   16
#define TILE_PIX 128
#define KCHUNK   64
#define NCHUNK  (C_DIM / KCHUNK)    // 8
#define NTILES  (HW_DIM / TILE_PIX) // 72

// ---------------- portable tensor-core wrappers (no sm_103a-only ISA) -------
static __device__ __forceinline__ void ldsm_x4(uint32_t* r, uint32_t addr) {
    asm volatile("ldmatrix.sync.aligned.m8n8.x4.shared.b16 {%0,%1,%2,%3}, [%4];"
                 : "=r"(r[0]), "=r"(r[1]), "=r"(r[2]), "=r"(r[3]) : "r"(addr));
}
static __device__ __forceinline__ void ldsm_x2_t(uint32_t* r, uint32_t addr) {
    asm volatile("ldmatrix.sync.aligned.m8n8.x2.trans.shared.b16 {%0,%1}, [%2];"
                 : "=r"(r[0]), "=r"(r[1]) : "r"(addr));
}
static __device__ __forceinline__ void mma_bf16(float* d, const uint32_t* a, const uint32_t* b) {
    asm volatile("mma.sync.aligned.m16n8k16.row.col.f32.bf16.bf16.f32 "
                 "{%0,%1,%2,%3}, {%4,%5,%6,%7}, {%8,%9}, {%0,%1,%2,%3};"
                 : "+f"(d[0]), "+f"(d[1]), "+f"(d[2]), "+f"(d[3])
                 : "r"(a[0]), "r"(a[1]), "r"(a[2]), "r"(a[3]), "r"(b[0]), "r"(b[1]));
}
static __device__ __forceinline__ uint32_t smem_u32(const void* p) {
    uint32_t a;
    asm("{ .reg .u64 t; cvta.to.shared.u64 t, %1; cvt.u32.u64 %0, t; }" : "=r"(a) : "l"(p));
    return a;
}

// weight tile images, SW128-XOR swizzled [chunk][hi|lo][128 o x 64 k bf16]
__device__ __align__(16) __nv_bfloat16 g_wt[NCHUNK][2][CH_DIM * KCHUNK];

__global__ void lcs_prep_w(const float* __restrict__ w1) {
    int idx = blockIdx.x * blockDim.x + threadIdx.x;   // 0..65535
    int o = idx >> 9;
    int c = idx & 511;
    int ch = c >> 6;
    int k  = c & 63;
    float w = w1[o * C_DIM + c];
    // truncation split: hi = w with low 16 mantissa bits cleared (exact bf16),
    // lo = rn(w - hi) captures the remainder to ~2^-25 rel.
    uint32_t wb;
    memcpy(&wb, &w, 4);
    uint32_t hb = wb & 0xFFFF0000u;
    float hf;
    memcpy(&hf, &hb, 4);
    __nv_bfloat16 hi = __ushort_as_bfloat16((unsigned short)(hb >> 16));
    __nv_bfloat16 lo = __float2bfloat16(w - hf);
    uint32_t off = (uint32_t)o * 128u + (uint32_t)k * 2u;      // [o][k] rows of 128B
    uint32_t sw  = off ^ ((off >> 3) & 0x70u);
    g_wt[ch][0][sw >> 1] = hi;
    g_wt[ch][1][sw >> 1] = lo;
}

// 64KB dynamic smem: [Wh 16K][Wl 16K][Xh 16K][Xl 16K]
extern __shared__ char dynsmem[];

__global__ __launch_bounds__(256, 2)
void lcs_main(const float* __restrict__ x,
              const float* __restrict__ b1,
              const float* __restrict__ w2,
              const float* __restrict__ b2,
              float* __restrict__ out) {
    __shared__ float logit_s[TILE_PIX];
    __shared__ __align__(16) float m0_s[TILE_PIX];
    __shared__ __align__(16) float m1_s[TILE_PIX];

    const int tid  = threadIdx.x;
    const int wid  = tid >> 5;
    const int lane = tid & 31;
    const int b    = blockIdx.x / NTILES;
    const int tile = blockIdx.x % NTILES;
    const int pix0 = tile * TILE_PIX;

    const float* xb = x + (size_t)b * C_DIM * HW_DIM + pix0;

    const uint32_t smem = smem_u32(dynsmem);
    const uint32_t sWh = smem, sWl = smem + 16384;
    const uint32_t sXh = smem + 32768, sXl = smem + 49152;

    if (tid < TILE_PIX) logit_s[tid] = 0.0f;

    // warp tile: wo in {0,1} -> 64 outs, wp in {0..3} -> 32 pixels
    const int wo = wid & 1;
    const int wp = wid >> 1;
    const int o0 = wo * 64;
    const int p0 = wp * 32;

    float acc[4][4][4];
#pragma unroll
    for (int mt = 0; mt < 4; mt++)
#pragma unroll
        for (int nt = 0; nt < 4; nt++)
#pragma unroll
            for (int q = 0; q < 4; q++) acc[mt][nt][q] = 0.0f;

    // ldmatrix A base offsets (per mt), before k-step add + swizzle:
    // off = row*128 + (lane>>4)*16,  row = o0 + mt*16 + (lane&15)
    uint32_t aBase[4];
#pragma unroll
    for (int mt = 0; mt < 4; mt++)
        aBase[mt] = (uint32_t)(o0 + mt * 16 + (lane & 15)) * 128u + (uint32_t)(lane >> 4) * 16u;

    for (int chunk = 0; chunk < NCHUNK; chunk++) {
        __syncthreads();   // previous chunk's smem reads complete

        // ---- W copy: 32KB pre-swizzled hi+lo images ----
        {
            const float4* wsrc = (const float4*)&g_wt[chunk][0][0];
            float4* wdst = (float4*)dynsmem;
#pragma unroll
            for (int i = 0; i < 8; i++) wdst[tid + i * 256] = wsrc[tid + i * 256];
        }
        // ---- X convert: fp32 -> bf16 hi/lo into [k][p] (256B rows, XOR swizzle) ----
        {
            const int c0 = chunk * KCHUNK;
#pragma unroll
            for (int kk = 0; kk < 8; kk++) {
                const int k = kk * 8 + wid;
                float4 v = *(const float4*)(xb + (size_t)(c0 + k) * HW_DIM + lane * 4);
                uint32_t b0, b1_, b2_, b3;
                memcpy(&b0, &v.x, 4); memcpy(&b1_, &v.y, 4);
                memcpy(&b2_, &v.z, 4); memcpy(&b3, &v.w, 4);
                uint32_t h01 = __byte_perm(b0, b1_, 0x7632);
                uint32_t h23 = __byte_perm(b2_, b3, 0x7632);
                uint32_t t0 = b0 & 0xFFFF0000u, t1 = b1_ & 0xFFFF0000u;
                uint32_t t2 = b2_ & 0xFFFF0000u, t3 = b3 & 0xFFFF0000u;
                float f0, f1, f2, f3;
                memcpy(&f0, &t0, 4); memcpy(&f1, &t1, 4);
                memcpy(&f2, &t2, 4); memcpy(&f3, &t3, 4);
                __nv_bfloat162 lo01 = __floats2bfloat162_rn(v.x - f0, v.y - f1);
                __nv_bfloat162 lo23 = __floats2bfloat162_rn(v.z - f2, v.w - f3);
                uint32_t l01, l23;
                memcpy(&l01, &lo01, 4); memcpy(&l23, &lo23, 4);
                uint32_t addr = (uint32_t)k * 256u
                              + (uint32_t)(((lane >> 1) ^ (k & 7)) << 4)
                              + (uint32_t)((lane & 1) << 3);
                asm volatile("st.shared.v2.b32 [%0], {%1,%2};" :: "r"(sXh + addr), "r"(h01), "r"(h23) : "memory");
                asm volatile("st.shared.v2.b32 [%0], {%1,%2};" :: "r"(sXl + addr), "r"(l01), "r"(l23) : "memory");
            }
        }
        __syncthreads();

        // ---- MMA: 4 k-steps of 16, 3 terms ----
#pragma unroll
        for (int ks = 0; ks < 4; ks++) {
            uint32_t ah[4][4], bh[4][2], bl[4][2];
#pragma unroll
            for (int mt = 0; mt < 4; mt++) {
                uint32_t off = aBase[mt] + (uint32_t)ks * 32u;
                ldsm_x4(ah[mt], sWh + (off ^ ((off >> 3) & 0x70u)));
            }
            const uint32_t kRow = (uint32_t)(ks * 16 + (lane & 15));
#pragma unroll
            for (int nt = 0; nt < 4; nt++) {
                uint32_t addr = kRow * 256u
                              + (uint32_t)((((uint32_t)(wp * 4 + nt)) ^ (kRow & 7u)) << 4);
                ldsm_x2_t(bh[nt], sXh + addr);
                ldsm_x2_t(bl[nt], sXl + addr);
            }
#pragma unroll
            for (int mt = 0; mt < 4; mt++)
#pragma unroll
                for (int nt = 0; nt < 4; nt++) {
                    mma_bf16(acc[mt][nt], ah[mt], bh[nt]);
                    mma_bf16(acc[mt][nt], ah[mt], bl[nt]);
                }
#pragma unroll
            for (int mt = 0; mt < 4; mt++) {
                uint32_t off = aBase[mt] + (uint32_t)ks * 32u;
                ldsm_x4(ah[mt], sWl + (off ^ ((off >> 3) & 0x70u)));
            }
#pragma unroll
            for (int mt = 0; mt < 4; mt++)
#pragma unroll
                for (int nt = 0; nt < 4; nt++)
                    mma_bf16(acc[mt][nt], ah[mt], bh[nt]);
        }
    }

    // ---- epilogue: logits d = sum_o (w2[0][o]-w2[1][o]) * relu(h + b1[o]) ----
    float wdv[8], b1v[8];
#pragma unroll
    for (int mt = 0; mt < 4; mt++)
#pragma unroll
        for (int h = 0; h < 2; h++) {
            int o = o0 + mt * 16 + (lane >> 2) + h * 8;
            wdv[mt * 2 + h] = w2[o] - w2[CH_DIM + o];
            b1v[mt * 2 + h] = b1[o];
        }

    float part[4][2];
#pragma unroll
    for (int nt = 0; nt < 4; nt++)
#pragma unroll
        for (int c = 0; c < 2; c++) {
            float s = 0.0f;
#pragma unroll
            for (int mt = 0; mt < 4; mt++)
#pragma unroll
                for (int h = 0; h < 2; h++)
                    s += wdv[mt * 2 + h] * fmaxf(acc[mt][nt][h * 2 + c] + b1v[mt * 2 + h], 0.0f);
            part[nt][c] = s;
        }
#pragma unroll
    for (int off = 4; off < 32; off <<= 1)
#pragma unroll
        for (int nt = 0; nt < 4; nt++)
#pragma unroll
            for (int c = 0; c < 2; c++)
                part[nt][c] += __shfl_xor_sync(0xFFFFFFFFu, part[nt][c], off);

    if (lane < 4) {
#pragma unroll
        for (int nt = 0; nt < 4; nt++)
#pragma unroll
            for (int c = 0; c < 2; c++)
                atomicAdd(&logit_s[p0 + nt * 8 + lane * 2 + c], part[nt][c]);
    }
    __syncthreads();

    const float db2 = b2[0] - b2[1];
    const size_t OFFX = (size_t)B_DIM * C_DIM * HW_DIM;
    if (tid < TILE_PIX) {
        float d  = logit_s[tid] + db2;
        float m0 = 1.0f / (1.0f + expf(-d));
        m0_s[tid] = m0;
        m1_s[tid] = 1.0f - m0;
        float* mout = out + 2 * OFFX + (size_t)b * 2 * HW_DIM + pix0 + tid;
        mout[0]      = m0;
        mout[HW_DIM] = 1.0f - m0;
    }
    __syncthreads();

    // ---- multiply sweep: x0 = x*m0, x1 = x*m1 (x tile L2-resident) ----
    float* out0 = out + (size_t)b * C_DIM * HW_DIM + pix0;
    float* out1 = out0 + OFFX;
    const float4* m0v4 = (const float4*)m0_s;
    const float4* m1v4 = (const float4*)m1_s;

    for (int it = tid; it < C_DIM * (TILE_PIX / 4); it += 256) {
        int c    = it >> 5;
        int col4 = it & 31;
        size_t off = (size_t)c * HW_DIM + col4 * 4;
        float4 xv  = *(const float4*)(xb + off);
        float4 m0v = m0v4[col4];
        float4 m1v = m1v4[col4];
        float4 r0 = make_float4(xv.x * m0v.x, xv.y * m0v.y, xv.z * m0v.z, xv.w * m0v.w);
        float4 r1 = make_float4(xv.x * m1v.x, xv.y * m1v.y, xv.z * m1v.z, xv.w * m1v.w);
        *(float4*)(out0 + off) = r0;
        *(float4*)(out1 + off) = r1;
    }
}

extern "C" void kernel_launch(void* const* d_in, const int* in_sizes, int n_in,
                              void* d_out, int out_size) {
    const float* x  = (const float*)d_in[0];
    const float* w1 = (const float*)d_in[1];
    const float* b1 = (const float*)d_in[2];
    const float* w2 = (const float*)d_in[3];
    const float* b2 = (const float*)d_in[4];
    float* out = (float*)d_out;

    cudaFuncSetAttribute(lcs_main, cudaFuncAttributeMaxDynamicSharedMemorySize, 65536);

    lcs_prep_w<<<256, 256>>>(w1);

    int nblocks = B_DIM * NTILES;   // 1152
    lcs_main<<<nblocks, 256, 65536>>>(x, b1, w2, b2, out);
}